// round 9
// baseline (speedup 1.0000x reference)
#include <cuda_runtime.h>

// Problem constants (fixed by the dataset problem)
#define BI 128    // batch
#define TT 128    // seq len
#define HH 1024   // hidden
#define G3 3072   // 3*H
#define KS 8      // split-K slices for M=128 GEMMs

// ---------------- scratch (static __device__ — no allocation allowed) ----------------
__device__ float g_gx  [(size_t)BI * TT * G3];   // gates_x for current GRU   (201 MB)
__device__ float g_Y   [(size_t)BI * TT * HH];   // premise outputs, [B,T,H]  (67 MB)
__device__ float g_Wy  [(size_t)BI * TT * HH];   // Y @ W_y                   (67 MB)
__device__ float g_part [(size_t)KS * BI * G3];  // split-K partials (gh / r@W_p)
__device__ float g_part2[(size_t)KS * BI * HH];  // split-K partials (Wh / h@W_x)
__device__ float g_h    [BI * HH];               // running hidden state
__device__ float g_Wh   [BI * HH];
__device__ float g_scores[BI * TT];
__device__ float g_alpha [BI * TT];
__device__ float g_r     [BI * HH];
__device__ float g_hstar [BI * HH];

// ---------------- packed f32x2 helpers (Blackwell FFMA2) ----------------
__device__ __forceinline__ unsigned long long pk2(float x, float y) {
    unsigned long long r;
    asm("mov.b64 %0, {%1, %2};" : "=l"(r) : "f"(x), "f"(y));
    return r;
}
__device__ __forceinline__ void fma2(unsigned long long& d, unsigned long long a, unsigned long long b) {
    asm("fma.rn.f32x2 %0, %1, %2, %0;" : "+l"(d) : "l"(a), "l"(b));
}
__device__ __forceinline__ float2 upk2(unsigned long long v) {
    float2 r;
    asm("mov.b64 {%0, %1}, %2;" : "=f"(r.x), "=f"(r.y) : "l"(v));
    return r;
}

// ---------------- tiled GEMM ----------------
// C[M,N] = A[M,K] * op(B)  (+ bias[N] when ADD_BIAS and gridDim.z==1)
//   NT=true : B is [N,K] row-major (C = A * B^T)
//   NT=false: B is [K,N] row-major (C = A * B)
// gridDim.z = split-K slices; slice z writes C + z*M*N.
template <int BM, int BN, int BK, int TM, int TN, bool NT, bool ADD_BIAS>
__global__ __launch_bounds__(256) void gemm_k(
    const float* __restrict__ A, const float* __restrict__ B,
    const float* __restrict__ bias, float* __restrict__ C,
    int M, int N, int K)
{
    constexpr int TX = BN / TN;       // 16
    constexpr int TY = BM / TM;       // 16
    constexpr int GA = TM / 4;        // 2
    constexpr int GB = TN / 4;        // 1 or 2

    const int tid = threadIdx.x;
    const int tx  = tid % TX;
    const int ty  = tid / TX;
    const int m0  = blockIdx.y * BM;
    const int n0  = blockIdx.x * BN;
    const int Ksl = K / gridDim.z;
    const int k0  = blockIdx.z * Ksl;
    const int KT  = Ksl / BK;

    __shared__ float As[BK][BM];
    __shared__ float Bs[BK][BN];

    // A tile loader: BM x BK, stored transposed As[k][m]
    const int arow = tid >> 1;
    const int acol = (tid & 1) * 4;
    const float* Aptr = A + (size_t)(m0 + arow) * K + k0 + acol;

    // B tile loader
    const float* Bptr = nullptr;
    int brow = 0, bcol = 0;
    bool bload = false;
    if constexpr (NT) {
        constexpr int NB4 = BN * BK / 4;
        bload = (tid < NB4);
        brow = tid >> 1;
        bcol = (tid & 1) * 4;
        if (bload) Bptr = B + (size_t)(n0 + brow) * K + k0 + bcol;
    } else {
        constexpr int NB4 = BK * BN / 4;
        constexpr int F4R = BN / 4;
        bload = (tid < NB4);
        brow = tid / F4R;
        bcol = (tid % F4R) * 4;
        if (bload) Bptr = B + (size_t)(k0 + brow) * N + n0 + bcol;
    }

    unsigned long long acc[TM][TN / 2];
#pragma unroll
    for (int i = 0; i < TM; i++)
#pragma unroll
        for (int j = 0; j < TN / 2; j++) acc[i][j] = 0ULL;

    float4 ra = make_float4(0.f, 0.f, 0.f, 0.f);
    float4 rb = make_float4(0.f, 0.f, 0.f, 0.f);
    ra = *(const float4*)(Aptr);
    if (bload) rb = *(const float4*)(Bptr);

    for (int kt = 0; kt < KT; ++kt) {
        __syncthreads();
        As[acol + 0][arow] = ra.x;
        As[acol + 1][arow] = ra.y;
        As[acol + 2][arow] = ra.z;
        As[acol + 3][arow] = ra.w;
        if constexpr (NT) {
            if (bload) {
                Bs[bcol + 0][brow] = rb.x;
                Bs[bcol + 1][brow] = rb.y;
                Bs[bcol + 2][brow] = rb.z;
                Bs[bcol + 3][brow] = rb.w;
            }
        } else {
            if (bload) *(float4*)&Bs[brow][bcol] = rb;
        }
        __syncthreads();

        if (kt + 1 < KT) {   // prefetch next tile into registers (hides LDG latency)
            ra = *(const float4*)(Aptr + (kt + 1) * BK);
            if (bload) {
                if constexpr (NT)
                    rb = *(const float4*)(Bptr + (kt + 1) * BK);
                else
                    rb = *(const float4*)(Bptr + (size_t)(kt + 1) * BK * N);
            }
        }

#pragma unroll
        for (int k = 0; k < BK; k++) {
            float4 a4[GA], b4[GB];
#pragma unroll
            for (int g = 0; g < GA; g++)
                a4[g] = *(const float4*)&As[k][g * (BM / GA) + ty * 4];
#pragma unroll
            for (int g = 0; g < GB; g++)
                b4[g] = *(const float4*)&Bs[k][g * (BN / GB) + tx * 4];

            unsigned long long av[TM], bv[TN / 2];
#pragma unroll
            for (int g = 0; g < GA; g++) {
                av[g * 4 + 0] = pk2(a4[g].x, a4[g].x);
                av[g * 4 + 1] = pk2(a4[g].y, a4[g].y);
                av[g * 4 + 2] = pk2(a4[g].z, a4[g].z);
                av[g * 4 + 3] = pk2(a4[g].w, a4[g].w);
            }
#pragma unroll
            for (int g = 0; g < GB; g++) {
                bv[g * 2 + 0] = pk2(b4[g].x, b4[g].y);
                bv[g * 2 + 1] = pk2(b4[g].z, b4[g].w);
            }
#pragma unroll
            for (int i = 0; i < TM; i++)
#pragma unroll
                for (int j = 0; j < TN / 2; j++)
                    fma2(acc[i][j], av[i], bv[j]);
        }
    }

    float* Co = C + (size_t)blockIdx.z * M * N;
#pragma unroll
    for (int gi = 0; gi < GA; gi++)
#pragma unroll
        for (int i = 0; i < 4; i++) {
            int row = m0 + gi * (BM / GA) + ty * 4 + i;
#pragma unroll
            for (int gj = 0; gj < GB; gj++)
#pragma unroll
                for (int jp = 0; jp < 2; jp++) {
                    float2 v = upk2(acc[gi * 4 + i][gj * 2 + jp]);
                    int col = n0 + gj * (BN / GB) + tx * 4 + jp * 2;
                    if (ADD_BIAS) {
                        v.x += bias[col];
                        v.y += bias[col + 1];
                    }
                    Co[(size_t)row * N + col + 0] = v.x;
                    Co[(size_t)row * N + col + 1] = v.y;
                }
        }
}

// ---------------- GRU pointwise update (fused gates) ----------------
__global__ void zero_h_k() {
    int i = blockIdx.x * 256 + threadIdx.x;
    g_h[i] = 0.f;
}

__device__ __forceinline__ float sigm(float x) { return 1.f / (1.f + expf(-x)); }

__global__ void gru_update_k(const float* __restrict__ bhh, int t, int writeY) {
    int idx = blockIdx.x * 256 + threadIdx.x;   // 0 .. 131071
    int b = idx >> 10;
    int j = idx & 1023;
    float gr = 0.f, gz = 0.f, gn = 0.f;
#pragma unroll
    for (int s = 0; s < KS; s++) {
        const float* p = g_part + (size_t)s * BI * G3 + (size_t)b * G3;
        gr += p[j];
        gz += p[1024 + j];
        gn += p[2048 + j];
    }
    gr += bhh[j];
    gz += bhh[1024 + j];
    gn += bhh[2048 + j];
    const float* gx = g_gx + ((size_t)b * TT + t) * G3;
    float xr = gx[j], xz = gx[1024 + j], xn = gx[2048 + j];
    float rg = sigm(xr + gr);
    float zg = sigm(xz + gz);
    float nn = tanhf(xn + rg * gn);
    float hp = g_h[idx];
    float hv = (1.f - zg) * nn + zg * hp;
    g_h[idx] = hv;
    if (writeY) g_Y[((size_t)b * TT + t) * HH + j] = hv;
}

// ---------------- attention / head kernels ----------------
__global__ void scores_k(const float* __restrict__ Walpha) {
    int bt = blockIdx.x;         // b*T + t
    int b = bt >> 7;
    int tid = threadIdx.x;
    const float* wy = g_Wy + (size_t)bt * HH;
    const float* wh = g_Wh + (size_t)b * HH;
    float p = 0.f;
    for (int h = tid; h < HH; h += 128)
        p += tanhf(wy[h] + wh[h]) * Walpha[h];
    __shared__ float red[128];
    red[tid] = p;
    __syncthreads();
    for (int s = 64; s > 0; s >>= 1) {
        if (tid < s) red[tid] += red[tid + s];
        __syncthreads();
    }
    if (tid == 0) g_scores[bt] = red[0];
}

__global__ void softmax_k() {
    int b = blockIdx.x, tid = threadIdx.x;
    __shared__ float red[128];
    __shared__ float mval, sval;
    float v = g_scores[b * TT + tid];
    red[tid] = v;
    __syncthreads();
    for (int s = 64; s > 0; s >>= 1) {
        if (tid < s) red[tid] = fmaxf(red[tid], red[tid + s]);
        __syncthreads();
    }
    if (tid == 0) mval = red[0];
    __syncthreads();
    float e = expf(v - mval);
    red[tid] = e;
    __syncthreads();
    for (int s = 64; s > 0; s >>= 1) {
        if (tid < s) red[tid] += red[tid + s];
        __syncthreads();
    }
    if (tid == 0) sval = red[0];
    __syncthreads();
    g_alpha[b * TT + tid] = e / sval;
}

__global__ void rvec_k() {
    int idx = blockIdx.x * 256 + threadIdx.x;   // one block spans a single b
    int b = (blockIdx.x * 256) >> 10;
    int h = idx & 1023;
    __shared__ float al[TT];
    if (threadIdx.x < TT) al[threadIdx.x] = g_alpha[b * TT + threadIdx.x];
    __syncthreads();
    const float* y = g_Y + (size_t)b * TT * HH + h;
    float acc = 0.f;
#pragma unroll 4
    for (int t = 0; t < TT; t++)
        acc += al[t] * y[(size_t)t * HH];
    g_r[idx] = acc;
}

// sums split-K partials; useA -> g_part, useB -> g_part2; dstSel 0->g_Wh 1->g_hstar
__global__ void reduce_k(int useA, int useB, int dotanh, int dstSel) {
    int i = blockIdx.x * 256 + threadIdx.x;   // count = BI*HH
    float v = 0.f;
    if (useA)
#pragma unroll
        for (int s = 0; s < KS; s++) v += g_part[(size_t)s * BI * HH + i];
    if (useB)
#pragma unroll
        for (int s = 0; s < KS; s++) v += g_part2[(size_t)s * BI * HH + i];
    if (dotanh) v = tanhf(v);
    float* dst = dstSel ? g_hstar : g_Wh;
    dst[i] = v;
}

__global__ void final_k(const float* __restrict__ outw, const float* __restrict__ outb,
                        float* __restrict__ out) {
    int b = blockIdx.x, tid = threadIdx.x;
    const float* hs = g_hstar + (size_t)b * HH;
    float p0 = 0.f, p1 = 0.f, p2 = 0.f;
    for (int h = tid; h < HH; h += 128) {
        float v = hs[h];
        p0 += v * outw[h];
        p1 += v * outw[HH + h];
        p2 += v * outw[2 * HH + h];
    }
    __shared__ float r0[128], r1[128], r2[128];
    r0[tid] = p0; r1[tid] = p1; r2[tid] = p2;
    __syncthreads();
    for (int s = 64; s > 0; s >>= 1) {
        if (tid < s) { r0[tid] += r0[tid + s]; r1[tid] += r1[tid + s]; r2[tid] += r2[tid + s]; }
        __syncthreads();
    }
    if (tid == 0) {
        float l0 = tanhf(r0[0] + outb[0]);
        float l1 = tanhf(r1[0] + outb[1]);
        float l2 = tanhf(r2[0] + outb[2]);
        float m = fmaxf(l0, fmaxf(l1, l2));
        float lse = m + logf(expf(l0 - m) + expf(l1 - m) + expf(l2 - m));
        out[b * 3 + 0] = l0 - lse;
        out[b * 3 + 1] = l1 - lse;
        out[b * 3 + 2] = l2 - lse;
    }
}

// ---------------- launch ----------------
extern "C" void kernel_launch(void* const* d_in, const int* in_sizes, int n_in,
                              void* d_out, int out_size)
{
    const float* premise    = (const float*)d_in[0];
    const float* hypothesis = (const float*)d_in[1];
    const float* p_Wih = (const float*)d_in[2];
    const float* p_Whh = (const float*)d_in[3];
    const float* p_bih = (const float*)d_in[4];
    const float* p_bhh = (const float*)d_in[5];
    const float* h_Wih = (const float*)d_in[6];
    const float* h_Whh = (const float*)d_in[7];
    const float* h_bih = (const float*)d_in[8];
    const float* h_bhh = (const float*)d_in[9];
    const float* W_y    = (const float*)d_in[10];
    const float* W_h    = (const float*)d_in[11];
    const float* W_alpha = (const float*)d_in[12];
    const float* W_x    = (const float*)d_in[13];
    const float* W_p    = (const float*)d_in[14];
    const float* out_w  = (const float*)d_in[15];
    const float* out_b  = (const float*)d_in[16];
    float* out = (float*)d_out;

    // Resolve scratch symbol addresses once (pure lookup, deterministic).
    static float *gx = nullptr, *Yb, *Wyb, *part, *part2, *hbuf, *rbuf;
    if (!gx) {
        cudaGetSymbolAddress((void**)&gx,    g_gx);
        cudaGetSymbolAddress((void**)&Yb,    g_Y);
        cudaGetSymbolAddress((void**)&Wyb,   g_Wy);
        cudaGetSymbolAddress((void**)&part,  g_part);
        cudaGetSymbolAddress((void**)&part2, g_part2);
        cudaGetSymbolAddress((void**)&hbuf,  g_h);
        cudaGetSymbolAddress((void**)&rbuf,  g_r);
    }

    const int MT = BI * TT;   // 16384

    // 1) gates_x for premise: gx[b*T+t, g] = premise[b,t,:] . p_Wih[g,:] + p_bih[g]
    gemm_k<128, 128, 8, 8, 8, true, true>
        <<<dim3(G3 / 128, MT / 128, 1), 256>>>(premise, p_Wih, p_bih, gx, MT, G3, HH);

    // 2) premise GRU
    zero_h_k<<<512, 256>>>();
    for (int t = 0; t < TT; t++) {
        gemm_k<128, 64, 8, 8, 4, true, false>
            <<<dim3(G3 / 64, 1, KS), 256>>>(hbuf, p_Whh, nullptr, part, BI, G3, HH);
        gru_update_k<<<512, 256>>>(p_bhh, t, 1);
    }

    // 3) gates_x for hypothesis (reuses gx — stream-ordered after premise steps)
    gemm_k<128, 128, 8, 8, 8, true, true>
        <<<dim3(G3 / 128, MT / 128, 1), 256>>>(hypothesis, h_Wih, h_bih, gx, MT, G3, HH);

    // 4) hypothesis GRU (h0 = premise h_n, carried in g_h); only final h needed
    for (int t = 0; t < TT; t++) {
        gemm_k<128, 64, 8, 8, 4, true, false>
            <<<dim3(G3 / 64, 1, KS), 256>>>(hbuf, h_Whh, nullptr, part, BI, G3, HH);
        gru_update_k<<<512, 256>>>(h_bhh, t, 0);
    }

    // 5) attention
    // Wy = Y @ W_y   [16384,1024] x [1024,1024]
    gemm_k<128, 128, 8, 8, 8, false, false>
        <<<dim3(HH / 128, MT / 128, 1), 256>>>(Yb, W_y, nullptr, Wyb, MT, HH, HH);
    // Wh = h_last @ W_h  (split-K partials then reduce)
    gemm_k<128, 64, 8, 8, 4, false, false>
        <<<dim3(HH / 64, 1, KS), 256>>>(hbuf, W_h, nullptr, part2, BI, HH, HH);
    reduce_k<<<512, 256>>>(0, 1, 0, 0);   // -> g_Wh
    scores_k<<<BI * TT, 128>>>(W_alpha);
    softmax_k<<<BI, 128>>>();
    rvec_k<<<512, 256>>>();               // -> g_r

    // 6) h_star = tanh(r @ W_p + h_last @ W_x)
    gemm_k<128, 64, 8, 8, 4, false, false>
        <<<dim3(HH / 64, 1, KS), 256>>>(rbuf, W_p, nullptr, part, BI, HH, HH);
    gemm_k<128, 64, 8, 8, 4, false, false>
        <<<dim3(HH / 64, 1, KS), 256>>>(hbuf, W_x, nullptr, part2, BI, HH, HH);
    reduce_k<<<512, 256>>>(1, 1, 1, 1);   // -> g_hstar

    // 7) logits + log_softmax
    final_k<<<BI, 128>>>(out_w, out_b, out);
}